// round 3
// baseline (speedup 1.0000x reference)
#include <cuda_runtime.h>
#include <cuda_fp16.h>
#include <cstdint>

// ---------------------------------------------------------------------------
// Problem constants
// ---------------------------------------------------------------------------
#define BATCH   8
#define TSTEPS  512
#define NEMBD   512
#define NHID    1024
#define VOCAB   32000
#define NROWS   (BATCH * TSTEPS)        // 4096
#define NG3     (3 * NHID)              // 3072

// GRU persistent kernel config
#define GRU_BLOCKS   128                // each owns 8 hidden columns
#define GRU_THREADS  512                // 16 warps, K=1024 split across warps
#define HS_STRIDE    1028               // 1024 + 4 pad: bank = (4b + ksub) all-distinct

// GRU SMEM layout (floats)
#define WSM_FLOATS   (NHID * 24)        // 24576: [k][24] (z:0-7, r:8-15, h:16-23)
#define HS_FLOATS    (BATCH * HS_STRIDE)// 8224
#define PBUF_FLOATS  (16 * 8 * 16)      // 2048
#define XBUF_FLOATS  192                // Xproj values for this step (8b x 24cols)
#define ZSM_FLOATS   64
#define HPSM_FLOATS  64
#define BSM_FLOATS   24
#define GRU_SMEM_FLOATS (WSM_FLOATS + HS_FLOATS + PBUF_FLOATS + XBUF_FLOATS + ZSM_FLOATS + HPSM_FLOATS + BSM_FLOATS)
#define GRU_SMEM_BYTES  (GRU_SMEM_FLOATS * 4)   // ~140.8 KB

// ---------------------------------------------------------------------------
// Device scratch (__device__ globals; host obtains addresses ONLY via
// cudaGetSymbolAddress — never name decay).
// ---------------------------------------------------------------------------
__device__ float               g_h[BATCH * NHID];            // carry h
__device__ float               g_rh[BATCH * NHID];           // r*h broadcast
__device__ __half              g_hs[(size_t)NROWS * NHID];   // hidden states (fp16)
__device__ __half              g_wlm[(size_t)NHID * VOCAB];  // lm head weights fp16
__device__ __half              g_emb[(size_t)NROWS * NEMBD]; // gathered embeddings fp16
__device__ __half              g_wx[(size_t)NEMBD * NG3];    // x-part weights fp16 [k][g*1024+j]
__device__ float               g_xp[(size_t)NROWS * NG3];    // precomputed x-projections
__device__ unsigned long long  g_ctrs[64];                   // barrier counters (0 and 16 used)
__device__ float               g_logits_fb[(size_t)NROWS * VOCAB];

// ---------------------------------------------------------------------------
// Grid barrier: release-add, acquire-poll. Cumulative counter -> replay-safe.
// ---------------------------------------------------------------------------
__device__ __forceinline__ void group_barrier(unsigned long long* ctr) {
    __syncthreads();
    if (threadIdx.x == 0) {
        unsigned long long one = 1ULL, old;
        asm volatile("atom.add.release.gpu.global.u64 %0, [%1], %2;"
                     : "=l"(old) : "l"(ctr), "l"(one) : "memory");
        unsigned long long target = ((old + 1ULL + (GRU_BLOCKS - 1)) / GRU_BLOCKS) * GRU_BLOCKS;
        unsigned long long cur;
        do {
            asm volatile("ld.acquire.gpu.global.u64 %0, [%1];"
                         : "=l"(cur) : "l"(ctr) : "memory");
        } while (cur < target);
    }
    __syncthreads();
}

// ---------------------------------------------------------------------------
// Gate dot-product phase over K=1024 (h part). 16 warps x 64 K each.
// lane = (ksub<<3)|b, ksub in [0,4), b in [0,8).
// ---------------------------------------------------------------------------
template<int NC, int COFF>
__device__ __forceinline__ void gate_phase(const float* __restrict__ wsm,
                                           const float* __restrict__ hsm,
                                           float* __restrict__ pbuf,
                                           int warp, int lane) {
    const int b    = lane & 7;
    const int ksub = lane >> 3;
    float acc[NC];
#pragma unroll
    for (int j = 0; j < NC; j++) acc[j] = 0.f;
    const int kbase = warp * 64;
#pragma unroll
    for (int i = 0; i < 16; i++) {
        int k = kbase + i * 4 + ksub;
        float xv = hsm[b * HS_STRIDE + k];
        const float* wr = wsm + k * 24 + COFF;
#pragma unroll
        for (int v = 0; v < NC / 4; v++) {
            float4 wv = *(const float4*)(wr + v * 4);
            acc[v * 4 + 0] += xv * wv.x;
            acc[v * 4 + 1] += xv * wv.y;
            acc[v * 4 + 2] += xv * wv.z;
            acc[v * 4 + 3] += xv * wv.w;
        }
    }
#pragma unroll
    for (int j = 0; j < NC; j++) {
        acc[j] += __shfl_xor_sync(0xffffffffu, acc[j], 8);
        acc[j] += __shfl_xor_sync(0xffffffffu, acc[j], 16);
    }
    if (ksub == 0) {
#pragma unroll
        for (int j = 0; j < NC; j++) pbuf[warp * 128 + b * 16 + j] = acc[j];
    }
}

// ---------------------------------------------------------------------------
// Persistent GRU scan (recurrent part only; x-projections precomputed in g_xp)
// ---------------------------------------------------------------------------
__global__ void __launch_bounds__(GRU_THREADS, 1)
gru_kernel(const float* __restrict__ start,
           const float* __restrict__ Wz, const float* __restrict__ bz,
           const float* __restrict__ Wr, const float* __restrict__ br,
           const float* __restrict__ Wh, const float* __restrict__ bh) {
    extern __shared__ float smem[];
    float* wsm  = smem;                     // [1024][24]
    float* hsm  = wsm  + WSM_FLOATS;        // [8][1028]
    float* pbuf = hsm  + HS_FLOATS;         // [16][8][16]
    float* xbuf = pbuf + PBUF_FLOATS;       // [8][24]
    float* zsm  = xbuf + XBUF_FLOATS;       // [8][8]
    float* hpsm = zsm  + ZSM_FLOATS;        // [8][8]
    float* bsm  = hpsm + HPSM_FLOATS;       // [24]

    const int tid     = threadIdx.x;
    const int warp    = tid >> 5;
    const int lane    = tid & 31;
    const int colbase = blockIdx.x * 8;

    // weights: h-part rows (512..1535) of Wz/Wr/Wh, cols colbase..+7
    for (int i = tid; i < NHID * 8; i += GRU_THREADS) {
        int k = i >> 3, j = i & 7;
        wsm[k * 24 + j]      = Wz[(size_t)(NEMBD + k) * NHID + colbase + j];
        wsm[k * 24 + 8 + j]  = Wr[(size_t)(NEMBD + k) * NHID + colbase + j];
        wsm[k * 24 + 16 + j] = Wh[(size_t)(NEMBD + k) * NHID + colbase + j];
    }
    if (tid < 8) {
        bsm[tid]      = bz[colbase + tid];
        bsm[8 + tid]  = br[colbase + tid];
        bsm[16 + tid] = bh[colbase + tid];
    }

    const float4* start4 = (const float4*)start;
    const float4* h4     = (const float4*)g_h;
    const float4* rh4    = (const float4*)g_rh;

    // Xproj prefetch mapping for tid<192: b = tid/24, rem = tid%24 (g*8+j)
    const int xb   = tid / 24;
    const int xrem = tid - xb * 24;

    for (int t = 0; t < TSTEPS; ++t) {
        // prefetch Xproj for this step (consumed after phase A)
        float xpre = 0.f;
        if (tid < 192)
            xpre = g_xp[((size_t)(xb * TSTEPS + t)) * NG3 + (xrem >> 3) * NHID + colbase + (xrem & 7)];

        // stage h (start at t==0)
#pragma unroll
        for (int i = tid; i < 2048; i += GRU_THREADS) {
            int b = i >> 8, j4 = i & 255;
            float4 v = (t == 0) ? start4[j4] : h4[b * 256 + j4];
            *(float4*)&hsm[b * HS_STRIDE + j4 * 4] = v;
        }
        __syncthreads();

        // ---- Phase A: z and r (16 cols) ----
        gate_phase<16, 0>(wsm, hsm, pbuf, warp, lane);
        if (tid < 192) xbuf[tid] = xpre;
        __syncthreads();

        if (tid < 128) {
            int b = tid >> 4, jj = tid & 15;
            float s = 0.f;
#pragma unroll
            for (int w = 0; w < 16; w++) s += pbuf[w * 128 + b * 16 + jj];
            if (jj < 8) {
                float z = 1.f / (1.f + __expf(-(s + xbuf[b * 24 + jj] + bsm[jj])));
                zsm[b * 8 + jj] = z;
            } else {
                int j = jj - 8;
                float hv = hsm[b * HS_STRIDE + colbase + j];
                hpsm[b * 8 + j] = hv;                       // cache h_prev for update
                float r = 1.f / (1.f + __expf(-(s + xbuf[b * 24 + 8 + j] + bsm[8 + j])));
                g_rh[b * NHID + colbase + j] = r * hv;
            }
        }
        group_barrier(&g_ctrs[0]);

        // stage r*h (overwrites hsm)
#pragma unroll
        for (int i = tid; i < 2048; i += GRU_THREADS) {
            int b = i >> 8, j4 = i & 255;
            *(float4*)&hsm[b * HS_STRIDE + j4 * 4] = rh4[b * 256 + j4];
        }
        __syncthreads();

        // ---- Phase B: hbar (8 cols) ----
        gate_phase<8, 16>(wsm, hsm, pbuf, warp, lane);
        __syncthreads();

        if (tid < 64) {
            int b = tid >> 3, j = tid & 7;
            float s = 0.f;
#pragma unroll
            for (int w = 0; w < 16; w++) s += pbuf[w * 128 + b * 16 + j];
            float hbar  = tanhf(s + xbuf[b * 24 + 16 + j] + bsm[16 + j]);
            float hprev = hpsm[b * 8 + j];
            float z     = zsm[b * 8 + j];
            float hn    = hprev + z * (hbar - hprev);
            int c = colbase + j;
            g_h[b * NHID + c] = hn;
            g_hs[(size_t)(b * TSTEPS + t) * NHID + c] = __float2half(hn);
        }
        group_barrier(&g_ctrs[16]);
    }
}

// ---------------------------------------------------------------------------
// Prep kernels
// ---------------------------------------------------------------------------
__global__ void cvt_half2(const float2* __restrict__ src, __half2* __restrict__ dst, int n2) {
    int i = blockIdx.x * blockDim.x + threadIdx.x;
    int stride = gridDim.x * blockDim.x;
    for (; i < n2; i += stride) {
        float2 v = src[i];
        dst[i] = __floats2half2_rn(v.x, v.y);
    }
}

// x-part weights -> fp16 [512][3072] with column layout g*1024+j
__global__ void build_wx(const float* __restrict__ Wz, const float* __restrict__ Wr,
                         const float* __restrict__ Wh, __half* __restrict__ dst) {
    int i = blockIdx.x * blockDim.x + threadIdx.x;   // over 512*3072
    if (i >= NEMBD * NG3) return;
    int k = i / NG3, c = i - k * NG3;
    int g = c >> 10, j = c & 1023;
    const float* W = (g == 0) ? Wz : ((g == 1) ? Wr : Wh);
    dst[i] = __float2half(W[(size_t)k * NHID + j]);
}

// embedding gather -> fp16 rows [4096][512], row = b*T+t
__global__ void gather_emb(const int* __restrict__ idx, const float* __restrict__ wte,
                           __half* __restrict__ dst) {
    int r = blockIdx.x;
    int tok = idx[r];
    float4 v = ((const float4*)(wte + (size_t)tok * NEMBD))[threadIdx.x];
    __half2* d = (__half2*)(dst + (size_t)r * NEMBD);
    d[threadIdx.x * 2]     = __floats2half2_rn(v.x, v.y);
    d[threadIdx.x * 2 + 1] = __floats2half2_rn(v.z, v.w);
}

// ---------------------------------------------------------------------------
// fp16 tensor-core GEMM: C[M,NCOLS] = A[M,KDIM] * B[KDIM,NCOLS] (+bias)
// 128x128x32 tiles, 8 warps, mma m16n8k16 f16->f32.
// ---------------------------------------------------------------------------
__device__ __forceinline__ void mma16816(float& c0, float& c1, float& c2, float& c3,
                                         unsigned a0, unsigned a1, unsigned a2, unsigned a3,
                                         unsigned b0, unsigned b1) {
    asm volatile(
        "mma.sync.aligned.m16n8k16.row.col.f32.f16.f16.f32 "
        "{%0,%1,%2,%3}, {%4,%5,%6,%7}, {%8,%9}, {%0,%1,%2,%3};\n"
        : "+f"(c0), "+f"(c1), "+f"(c2), "+f"(c3)
        : "r"(a0), "r"(a1), "r"(a2), "r"(a3), "r"(b0), "r"(b1));
}

#define AS_STRIDE 40
#define BS_STRIDE 42

template<int KDIM, int NCOLS, bool HAS_BIAS>
__global__ void __launch_bounds__(256)
gemm_kernel(const __half* __restrict__ A, const __half* __restrict__ Bw,
            const float* __restrict__ bias, float* __restrict__ C) {
    const int bx = blockIdx.x, by = blockIdx.y;
    const int tid = threadIdx.x, warp = tid >> 5, lane = tid & 31;
    const int wm = warp >> 2, wn = warp & 3;
    __shared__ __half As[128 * AS_STRIDE];
    __shared__ __half Bs[128 * BS_STRIDE];

    float acc[4][4][4];
#pragma unroll
    for (int a = 0; a < 4; a++)
#pragma unroll
        for (int b = 0; b < 4; b++)
#pragma unroll
            for (int c = 0; c < 4; c++) acc[a][b][c] = 0.f;

    const int m0 = by * 128, n0 = bx * 128;

    for (int k0 = 0; k0 < KDIM; k0 += 32) {
#pragma unroll
        for (int i = tid; i < 512; i += 256) {
            int row = i >> 2, seg = i & 3;
            *(uint4*)&As[row * AS_STRIDE + seg * 8] =
                *(const uint4*)&A[(size_t)(m0 + row) * KDIM + k0 + seg * 8];
        }
#pragma unroll
        for (int i = tid; i < 2048; i += 256) {
            int k = i >> 6, np = i & 63;
            __half2 h2 = *(const __half2*)(Bw + (size_t)(k0 + k) * NCOLS + n0 + np * 2);
            Bs[(np * 2)     * BS_STRIDE + k] = __low2half(h2);
            Bs[(np * 2 + 1) * BS_STRIDE + k] = __high2half(h2);
        }
        __syncthreads();

#pragma unroll
        for (int kk = 0; kk < 2; kk++) {
            unsigned a[4][4], b[4][2];
            const int kc = kk * 16 + (lane & 3) * 2;
            const int r  = lane >> 2;
#pragma unroll
            for (int mt = 0; mt < 4; mt++) {
                int rr = wm * 64 + mt * 16 + r;
                a[mt][0] = *(const unsigned*)&As[rr * AS_STRIDE + kc];
                a[mt][1] = *(const unsigned*)&As[(rr + 8) * AS_STRIDE + kc];
                a[mt][2] = *(const unsigned*)&As[rr * AS_STRIDE + kc + 8];
                a[mt][3] = *(const unsigned*)&As[(rr + 8) * AS_STRIDE + kc + 8];
            }
#pragma unroll
            for (int nt = 0; nt < 4; nt++) {
                int nn = wn * 32 + nt * 8 + r;
                b[nt][0] = *(const unsigned*)&Bs[nn * BS_STRIDE + kc];
                b[nt][1] = *(const unsigned*)&Bs[nn * BS_STRIDE + kc + 8];
            }
#pragma unroll
            for (int mt = 0; mt < 4; mt++)
#pragma unroll
                for (int nt = 0; nt < 4; nt++)
                    mma16816(acc[mt][nt][0], acc[mt][nt][1], acc[mt][nt][2], acc[mt][nt][3],
                             a[mt][0], a[mt][1], a[mt][2], a[mt][3], b[nt][0], b[nt][1]);
        }
        __syncthreads();
    }

#pragma unroll
    for (int mt = 0; mt < 4; mt++) {
#pragma unroll
        for (int nt = 0; nt < 4; nt++) {
            int gr = m0 + wm * 64 + mt * 16 + (lane >> 2);
            int gc = n0 + wn * 32 + nt * 8 + (lane & 3) * 2;
            float b0 = 0.f, b1 = 0.f;
            if (HAS_BIAS) { b0 = bias[gc]; b1 = bias[gc + 1]; }
            float2 v0 = make_float2(acc[mt][nt][0] + b0, acc[mt][nt][1] + b1);
            float2 v1 = make_float2(acc[mt][nt][2] + b0, acc[mt][nt][3] + b1);
            *(float2*)&C[(size_t)gr * NCOLS + gc]       = v0;
            *(float2*)&C[(size_t)(gr + 8) * NCOLS + gc] = v1;
        }
    }
}

// ---------------------------------------------------------------------------
// Loss: per-row online logsumexp, mean NLL via atomicAdd
// ---------------------------------------------------------------------------
__global__ void __launch_bounds__(256)
loss_kernel(const float* __restrict__ logits, const int* __restrict__ targets,
            float* __restrict__ out_loss) {
    const int row = blockIdx.x;
    const float* lr = logits + (size_t)row * VOCAB;
    const int tid = threadIdx.x;

    float m = -1e30f, s = 0.f;
    for (int i = tid; i < VOCAB; i += 256) {
        float v = lr[i];
        float nm = fmaxf(m, v);
        s = s * __expf(m - nm) + __expf(v - nm);
        m = nm;
    }
    __shared__ float sm_m[256], sm_s[256];
    sm_m[tid] = m; sm_s[tid] = s;
    __syncthreads();
    for (int off = 128; off > 0; off >>= 1) {
        if (tid < off) {
            float m2 = sm_m[tid + off], s2 = sm_s[tid + off];
            float m1 = sm_m[tid],       s1 = sm_s[tid];
            float nm = fmaxf(m1, m2);
            sm_s[tid] = s1 * __expf(m1 - nm) + s2 * __expf(m2 - nm);
            sm_m[tid] = nm;
        }
        __syncthreads();
    }
    if (tid == 0) {
        float lse = sm_m[0] + logf(sm_s[0]);
        float tl  = lr[targets[row]];
        atomicAdd(out_loss, (lse - tl) * (1.0f / (float)NROWS));
    }
}

// ---------------------------------------------------------------------------
// Host entry
// ---------------------------------------------------------------------------
extern "C" void kernel_launch(void* const* d_in, const int* in_sizes, int n_in,
                              void* d_out, int out_size) {
    const int*   idx   = (const int*)d_in[0];
    const int*   tgt   = (const int*)d_in[1];
    const float* wte   = (const float*)d_in[2];
    const float* start = (const float*)d_in[3];
    const float* Wz    = (const float*)d_in[4];
    const float* bz    = (const float*)d_in[5];
    const float* Wr    = (const float*)d_in[6];
    const float* br    = (const float*)d_in[7];
    const float* Wh    = (const float*)d_in[8];
    const float* bh    = (const float*)d_in[9];
    const float* lmW   = (const float*)d_in[10];
    const float* lmb   = (const float*)d_in[11];

    void *p_hs, *p_wlm, *p_fb, *p_emb, *p_wx, *p_xp;
    cudaGetSymbolAddress(&p_hs,  g_hs);
    cudaGetSymbolAddress(&p_wlm, g_wlm);
    cudaGetSymbolAddress(&p_fb,  g_logits_fb);
    cudaGetSymbolAddress(&p_emb, g_emb);
    cudaGetSymbolAddress(&p_wx,  g_wx);
    cudaGetSymbolAddress(&p_xp,  g_xp);
    __half* d_hs  = (__half*)p_hs;
    __half* d_wlm = (__half*)p_wlm;
    float*  d_fb  = (float*)p_fb;
    __half* d_emb = (__half*)p_emb;
    __half* d_wx  = (__half*)p_wx;
    float*  d_xp  = (float*)p_xp;

    cudaFuncSetAttribute(gru_kernel, cudaFuncAttributeMaxDynamicSharedMemorySize,
                         GRU_SMEM_BYTES);

    // 1) prep: fp16 x-part weights + gathered embeddings
    build_wx<<<(NEMBD * NG3 + 255) / 256, 256>>>(Wz, Wr, Wh, d_wx);
    gather_emb<<<NROWS, 128>>>(idx, wte, d_emb);

    // 2) Xproj[4096,3072] = emb @ Wx  (biases added inside GRU)
    gemm_kernel<NEMBD, NG3, false><<<dim3(NG3 / 128, NROWS / 128), 256>>>(
        d_emb, d_wx, nullptr, d_xp);

    // 3) persistent GRU scan (recurrent part, K=1024)
    gru_kernel<<<GRU_BLOCKS, GRU_THREADS, GRU_SMEM_BYTES>>>(start, Wz, bz, Wr, br, Wh, bh);

    // 4) lm head weights fp16 + GEMM
    cvt_half2<<<4096, 256>>>((const float2*)lmW, (__half2*)d_wlm, (NHID * VOCAB) / 2);
    const long long NL = (long long)NROWS * VOCAB;
    float* fo = (float*)d_out;
    float* logits = ((long long)out_size >= NL) ? fo : d_fb;
    gemm_kernel<NHID, VOCAB, true><<<dim3(VOCAB / 128, NROWS / 128), 256>>>(
        d_hs, d_wlm, lmb, logits);

    // 5) loss
    float* loss_ptr = nullptr;
    if ((long long)out_size >= NL + 1)      loss_ptr = fo + NL;
    else if ((long long)out_size < NL)      loss_ptr = fo;
    if (loss_ptr) {
        cudaMemsetAsync(loss_ptr, 0, sizeof(float));
        loss_kernel<<<NROWS, 256>>>(logits, tgt, loss_ptr);
    }
}

// round 4
// speedup vs baseline: 1.7983x; 1.7983x over previous
#include <cuda_runtime.h>
#include <cuda_fp16.h>
#include <cstdint>

// ---------------------------------------------------------------------------
// Problem constants
// ---------------------------------------------------------------------------
#define BATCH   8
#define TSTEPS  512
#define NEMBD   512
#define NHID    1024
#define VOCAB   32000
#define NROWS   (BATCH * TSTEPS)        // 4096
#define NG3     (3 * NHID)              // 3072

// GRU persistent kernel config
#define GRU_BLOCKS   128                // each owns 8 hidden columns
#define GRU_THREADS  512                // 16 warps; K=1024 -> 64 per warp
#define WK          1032                // half-stride for weight/h rows (4-bank spacing)

// GRU SMEM layout (bytes)
#define WSM_BYTES   (24 * WK * 2)       // 49536  fp16 weights [gate*8+col][k]
#define HSM_BYTES   (8  * WK * 2)       // 16512  fp16 staged h / r*h rows 0-7
#define PBUF_BYTES  (16 * 2 * 64 * 4)   // 8192   fp32 partials [warp][gate][64]
#define XBUF_BYTES  (192 * 4)
#define ZSM_BYTES   (64 * 4)
#define HPSM_BYTES  (64 * 4)
#define BSM_BYTES   (24 * 4)
#define GRU_SMEM_BYTES (WSM_BYTES + HSM_BYTES + PBUF_BYTES + XBUF_BYTES + ZSM_BYTES + HPSM_BYTES + BSM_BYTES)

// ---------------------------------------------------------------------------
// Device scratch (host resolves ONLY via cudaGetSymbolAddress)
// ---------------------------------------------------------------------------
__device__ __half              g_h16[BATCH * NHID];          // carry h (fp16 broadcast copy)
__device__ __half              g_rh16[BATCH * NHID];         // r*h broadcast (fp16)
__device__ __half              g_hs[(size_t)NROWS * NHID];   // hidden states (fp16)
__device__ __half              g_wlm[(size_t)NHID * VOCAB];  // lm head weights fp16
__device__ __half              g_emb[(size_t)NROWS * NEMBD]; // gathered embeddings fp16
__device__ __half              g_wx[(size_t)NEMBD * NG3];    // x-part weights fp16
__device__ float               g_xp[(size_t)NROWS * NG3];    // precomputed x-projections
__device__ unsigned long long  g_ctrs[256];                  // barrier counters: [0], [128] (1KB apart)
__device__ float               g_logits_fb[(size_t)NROWS * VOCAB];

// ---------------------------------------------------------------------------
// Grid barrier: release-add, acquire-poll WITH nanosleep backoff (anti-flood).
// Cumulative counter -> graph-replay-safe.
// ---------------------------------------------------------------------------
__device__ __forceinline__ void group_barrier(unsigned long long* ctr) {
    __syncthreads();
    if (threadIdx.x == 0) {
        unsigned long long one = 1ULL, old;
        asm volatile("atom.add.release.gpu.global.u64 %0, [%1], %2;"
                     : "=l"(old) : "l"(ctr), "l"(one) : "memory");
        unsigned long long target = ((old + 1ULL + (GRU_BLOCKS - 1)) / GRU_BLOCKS) * GRU_BLOCKS;
        unsigned long long cur;
        asm volatile("ld.acquire.gpu.global.u64 %0, [%1];" : "=l"(cur) : "l"(ctr) : "memory");
        while (cur < target) {
            __nanosleep(64);
            asm volatile("ld.acquire.gpu.global.u64 %0, [%1];" : "=l"(cur) : "l"(ctr) : "memory");
        }
    }
    __syncthreads();
}

// ---------------------------------------------------------------------------
// mma m16n8k16 f16 -> f32
// ---------------------------------------------------------------------------
__device__ __forceinline__ void mma16816(float& c0, float& c1, float& c2, float& c3,
                                         unsigned a0, unsigned a1, unsigned a2, unsigned a3,
                                         unsigned b0, unsigned b1) {
    asm volatile(
        "mma.sync.aligned.m16n8k16.row.col.f32.f16.f16.f32 "
        "{%0,%1,%2,%3}, {%4,%5,%6,%7}, {%8,%9}, {%0,%1,%2,%3};\n"
        : "+f"(c0), "+f"(c1), "+f"(c2), "+f"(c3)
        : "r"(a0), "r"(a1), "r"(a2), "r"(a3), "r"(b0), "r"(b1));
}

// ---------------------------------------------------------------------------
// Persistent GRU scan. Block owns hidden cols [colbase, colbase+8).
// Gates via tensor cores: batch rows 0-7 real, rows 8-15 implicit zeros.
// ---------------------------------------------------------------------------
__global__ void __launch_bounds__(GRU_THREADS, 1)
gru_kernel(const float* __restrict__ start,
           const float* __restrict__ Wz, const float* __restrict__ bz,
           const float* __restrict__ Wr, const float* __restrict__ br,
           const float* __restrict__ Wh, const float* __restrict__ bh) {
    extern __shared__ char smem[];
    __half* wsm  = (__half*)smem;                          // [24][WK]
    __half* hsm  = (__half*)(smem + WSM_BYTES);            // [8][WK]
    float*  pbuf = (float*)(smem + WSM_BYTES + HSM_BYTES); // [16][2][64]
    float*  xbuf = pbuf + 16 * 2 * 64;                     // [192]
    float*  zsm  = xbuf + 192;                             // [64]
    float*  hpsm = zsm + 64;                               // [64] fp32 carried h (owned cols)
    float*  bsm  = hpsm + 64;                              // [24]

    const int tid     = threadIdx.x;
    const int warp    = tid >> 5;
    const int lane    = tid & 31;
    const int colbase = blockIdx.x * 8;

    // --- init ---
    for (int i = tid; i < 24 * 1024; i += GRU_THREADS) {
        int j = i >> 10, k = i & 1023;                     // j = gate*8+col
        int g = j >> 3;
        const float* W = (g == 0) ? Wz : ((g == 1) ? Wr : Wh);
        wsm[j * WK + k] = __float2half(W[(size_t)(NEMBD + k) * NHID + colbase + (j & 7)]);
    }
    if (tid < 24) bsm[tid] = (tid < 8 ? bz[colbase + tid]
                              : tid < 16 ? br[colbase + tid - 8]
                                         : bh[colbase + tid - 16]);
    if (tid < 64) hpsm[tid] = start[colbase + (tid & 7)];  // broadcast over batch

    const float4* start4 = (const float4*)start;
    const uint4*  h16v   = (const uint4*)g_h16;
    const uint4*  rh16v  = (const uint4*)g_rh16;

    const int xb   = tid / 24;                  // tid<192: batch
    const int xrem = tid - xb * 24;             // gate*8+j

    const int frow = lane >> 2;                 // 0..7
    const int fk   = (lane & 3) * 2;

    for (int t = 0; t < TSTEPS; ++t) {
        float xpre = 0.f;
        if (tid < 192)
            xpre = g_xp[((size_t)(xb * TSTEPS + t)) * NG3 + (xrem >> 3) * NHID + colbase + (xrem & 7)];

        // ---- stage h rows 0-7 (fp16) ----
        if (t == 0) {
            for (int i = tid; i < 1024; i += GRU_THREADS) {
                int b = i >> 7, seg = i & 127;
                float4 v0 = start4[seg * 2], v1 = start4[seg * 2 + 1];
                __half2 h0 = __floats2half2_rn(v0.x, v0.y);
                __half2 h1 = __floats2half2_rn(v0.z, v0.w);
                __half2 h2 = __floats2half2_rn(v1.x, v1.y);
                __half2 h3 = __floats2half2_rn(v1.z, v1.w);
                uint4 u;
                u.x = *(unsigned*)&h0; u.y = *(unsigned*)&h1;
                u.z = *(unsigned*)&h2; u.w = *(unsigned*)&h3;
                *(uint4*)&hsm[b * WK + seg * 8] = u;
            }
        } else {
            for (int i = tid; i < 1024; i += GRU_THREADS) {
                int b = i >> 7, seg = i & 127;
                *(uint4*)&hsm[b * WK + seg * 8] = h16v[b * 128 + seg];
            }
        }
        __syncthreads();

        // ---- Phase A: z (gate0) and r (gate1) ----
        {
            float cz0 = 0, cz1 = 0, cz2 = 0, cz3 = 0;
            float cr0 = 0, cr1 = 0, cr2 = 0, cr3 = 0;
            const int kw = warp * 64;
#pragma unroll
            for (int c = 0; c < 4; c++) {
                int k0 = kw + c * 16;
                unsigned a0 = *(const unsigned*)&hsm[frow * WK + k0 + fk];
                unsigned a2 = *(const unsigned*)&hsm[frow * WK + k0 + 8 + fk];
                unsigned bz0 = *(const unsigned*)&wsm[frow * WK + k0 + fk];
                unsigned bz1 = *(const unsigned*)&wsm[frow * WK + k0 + 8 + fk];
                unsigned br0 = *(const unsigned*)&wsm[(8 + frow) * WK + k0 + fk];
                unsigned br1 = *(const unsigned*)&wsm[(8 + frow) * WK + k0 + 8 + fk];
                mma16816(cz0, cz1, cz2, cz3, a0, 0u, a2, 0u, bz0, bz1);
                mma16816(cr0, cr1, cr2, cr3, a0, 0u, a2, 0u, br0, br1);
            }
            pbuf[(warp * 2 + 0) * 64 + frow * 8 + fk]     = cz0;
            pbuf[(warp * 2 + 0) * 64 + frow * 8 + fk + 1] = cz1;
            pbuf[(warp * 2 + 1) * 64 + frow * 8 + fk]     = cr0;
            pbuf[(warp * 2 + 1) * 64 + frow * 8 + fk + 1] = cr1;
        }
        if (tid < 192) xbuf[tid] = xpre;
        __syncthreads();

        if (tid < 128) {
            int b = tid >> 4, jj = tid & 15;
            int g = jj >> 3, j = jj & 7;
            float s = 0.f;
#pragma unroll
            for (int w = 0; w < 16; w++) s += pbuf[(w * 2 + g) * 64 + b * 8 + j];
            if (g == 0) {
                float z = 1.f / (1.f + __expf(-(s + xbuf[b * 24 + j] + bsm[j])));
                zsm[b * 8 + j] = z;
            } else {
                float r = 1.f / (1.f + __expf(-(s + xbuf[b * 24 + 8 + j] + bsm[8 + j])));
                g_rh16[b * NHID + colbase + j] = __float2half(r * hpsm[b * 8 + j]);
            }
        }
        group_barrier(&g_ctrs[0]);

        // ---- stage r*h ----
        for (int i = tid; i < 1024; i += GRU_THREADS) {
            int b = i >> 7, seg = i & 127;
            *(uint4*)&hsm[b * WK + seg * 8] = rh16v[b * 128 + seg];
        }
        __syncthreads();

        // ---- Phase B: hbar (gate2) ----
        {
            float ch0 = 0, ch1 = 0, ch2 = 0, ch3 = 0;
            const int kw = warp * 64;
#pragma unroll
            for (int c = 0; c < 4; c++) {
                int k0 = kw + c * 16;
                unsigned a0 = *(const unsigned*)&hsm[frow * WK + k0 + fk];
                unsigned a2 = *(const unsigned*)&hsm[frow * WK + k0 + 8 + fk];
                unsigned bh0 = *(const unsigned*)&wsm[(16 + frow) * WK + k0 + fk];
                unsigned bh1 = *(const unsigned*)&wsm[(16 + frow) * WK + k0 + 8 + fk];
                mma16816(ch0, ch1, ch2, ch3, a0, 0u, a2, 0u, bh0, bh1);
            }
            pbuf[(warp * 2) * 64 + frow * 8 + fk]     = ch0;
            pbuf[(warp * 2) * 64 + frow * 8 + fk + 1] = ch1;
        }
        __syncthreads();

        if (tid < 64) {
            int b = tid >> 3, j = tid & 7;
            float s = 0.f;
#pragma unroll
            for (int w = 0; w < 16; w++) s += pbuf[(w * 2) * 64 + b * 8 + j];
            float hbar  = tanhf(s + xbuf[b * 24 + 16 + j] + bsm[16 + j]);
            float hprev = hpsm[tid];
            float z     = zsm[tid];
            float hn    = hprev + z * (hbar - hprev);
            hpsm[tid] = hn;
            __half hh = __float2half(hn);
            int c = colbase + j;
            g_h16[b * NHID + c] = hh;
            g_hs[(size_t)(b * TSTEPS + t) * NHID + c] = hh;
        }
        group_barrier(&g_ctrs[128]);
    }
}

// ---------------------------------------------------------------------------
// Prep kernels
// ---------------------------------------------------------------------------
__global__ void cvt_half2(const float2* __restrict__ src, __half2* __restrict__ dst, int n2) {
    int i = blockIdx.x * blockDim.x + threadIdx.x;
    int stride = gridDim.x * blockDim.x;
    for (; i < n2; i += stride) {
        float2 v = src[i];
        dst[i] = __floats2half2_rn(v.x, v.y);
    }
}

__global__ void build_wx(const float* __restrict__ Wz, const float* __restrict__ Wr,
                         const float* __restrict__ Wh, __half* __restrict__ dst) {
    int i = blockIdx.x * blockDim.x + threadIdx.x;
    if (i >= NEMBD * NG3) return;
    int k = i / NG3, c = i - k * NG3;
    int g = c >> 10, j = c & 1023;
    const float* W = (g == 0) ? Wz : ((g == 1) ? Wr : Wh);
    dst[i] = __float2half(W[(size_t)k * NHID + j]);
}

__global__ void gather_emb(const int* __restrict__ idx, const float* __restrict__ wte,
                           __half* __restrict__ dst) {
    int r = blockIdx.x;
    int tok = idx[r];
    float4 v = ((const float4*)(wte + (size_t)tok * NEMBD))[threadIdx.x];
    __half2* d = (__half2*)(dst + (size_t)r * NEMBD);
    d[threadIdx.x * 2]     = __floats2half2_rn(v.x, v.y);
    d[threadIdx.x * 2 + 1] = __floats2half2_rn(v.z, v.w);
}

// ---------------------------------------------------------------------------
// fp16 tensor-core GEMM: C[M,NCOLS] = A[M,KDIM] * B[KDIM,NCOLS] (+bias)
// ---------------------------------------------------------------------------
#define AS_STRIDE 40
#define BS_STRIDE 42

template<int KDIM, int NCOLS, bool HAS_BIAS>
__global__ void __launch_bounds__(256)
gemm_kernel(const __half* __restrict__ A, const __half* __restrict__ Bw,
            const float* __restrict__ bias, float* __restrict__ C) {
    const int bx = blockIdx.x, by = blockIdx.y;
    const int tid = threadIdx.x, warp = tid >> 5, lane = tid & 31;
    const int wm = warp >> 2, wn = warp & 3;
    __shared__ __half As[128 * AS_STRIDE];
    __shared__ __half Bs[128 * BS_STRIDE];

    float acc[4][4][4];
#pragma unroll
    for (int a = 0; a < 4; a++)
#pragma unroll
        for (int b = 0; b < 4; b++)
#pragma unroll
            for (int c = 0; c < 4; c++) acc[a][b][c] = 0.f;

    const int m0 = by * 128, n0 = bx * 128;

    for (int k0 = 0; k0 < KDIM; k0 += 32) {
#pragma unroll
        for (int i = tid; i < 512; i += 256) {
            int row = i >> 2, seg = i & 3;
            *(uint4*)&As[row * AS_STRIDE + seg * 8] =
                *(const uint4*)&A[(size_t)(m0 + row) * KDIM + k0 + seg * 8];
        }
#pragma unroll
        for (int i = tid; i < 2048; i += 256) {
            int k = i >> 6, np = i & 63;
            __half2 h2 = *(const __half2*)(Bw + (size_t)(k0 + k) * NCOLS + n0 + np * 2);
            Bs[(np * 2)     * BS_STRIDE + k] = __low2half(h2);
            Bs[(np * 2 + 1) * BS_STRIDE + k] = __high2half(h2);
        }
        __syncthreads();

#pragma unroll
        for (int kk = 0; kk < 2; kk++) {
            unsigned a[4][4], b[4][2];
            const int kc = kk * 16 + (lane & 3) * 2;
            const int r  = lane >> 2;
#pragma unroll
            for (int mt = 0; mt < 4; mt++) {
                int rr = wm * 64 + mt * 16 + r;
                a[mt][0] = *(const unsigned*)&As[rr * AS_STRIDE + kc];
                a[mt][1] = *(const unsigned*)&As[(rr + 8) * AS_STRIDE + kc];
                a[mt][2] = *(const unsigned*)&As[rr * AS_STRIDE + kc + 8];
                a[mt][3] = *(const unsigned*)&As[(rr + 8) * AS_STRIDE + kc + 8];
            }
#pragma unroll
            for (int nt = 0; nt < 4; nt++) {
                int nn = wn * 32 + nt * 8 + r;
                b[nt][0] = *(const unsigned*)&Bs[nn * BS_STRIDE + kc];
                b[nt][1] = *(const unsigned*)&Bs[nn * BS_STRIDE + kc + 8];
            }
#pragma unroll
            for (int mt = 0; mt < 4; mt++)
#pragma unroll
                for (int nt = 0; nt < 4; nt++)
                    mma16816(acc[mt][nt][0], acc[mt][nt][1], acc[mt][nt][2], acc[mt][nt][3],
                             a[mt][0], a[mt][1], a[mt][2], a[mt][3], b[nt][0], b[nt][1]);
        }
        __syncthreads();
    }

#pragma unroll
    for (int mt = 0; mt < 4; mt++) {
#pragma unroll
        for (int nt = 0; nt < 4; nt++) {
            int gr = m0 + wm * 64 + mt * 16 + (lane >> 2);
            int gc = n0 + wn * 32 + nt * 8 + (lane & 3) * 2;
            float b0 = 0.f, b1 = 0.f;
            if (HAS_BIAS) { b0 = bias[gc]; b1 = bias[gc + 1]; }
            float2 v0 = make_float2(acc[mt][nt][0] + b0, acc[mt][nt][1] + b1);
            float2 v1 = make_float2(acc[mt][nt][2] + b0, acc[mt][nt][3] + b1);
            *(float2*)&C[(size_t)gr * NCOLS + gc]       = v0;
            *(float2*)&C[(size_t)(gr + 8) * NCOLS + gc] = v1;
        }
    }
}

// ---------------------------------------------------------------------------
// Loss
// ---------------------------------------------------------------------------
__global__ void __launch_bounds__(256)
loss_kernel(const float* __restrict__ logits, const int* __restrict__ targets,
            float* __restrict__ out_loss) {
    const int row = blockIdx.x;
    const float* lr = logits + (size_t)row * VOCAB;
    const int tid = threadIdx.x;

    float m = -1e30f, s = 0.f;
    for (int i = tid; i < VOCAB; i += 256) {
        float v = lr[i];
        float nm = fmaxf(m, v);
        s = s * __expf(m - nm) + __expf(v - nm);
        m = nm;
    }
    __shared__ float sm_m[256], sm_s[256];
    sm_m[tid] = m; sm_s[tid] = s;
    __syncthreads();
    for (int off = 128; off > 0; off >>= 1) {
        if (tid < off) {
            float m2 = sm_m[tid + off], s2 = sm_s[tid + off];
            float m1 = sm_m[tid],       s1 = sm_s[tid];
            float nm = fmaxf(m1, m2);
            sm_s[tid] = s1 * __expf(m1 - nm) + s2 * __expf(m2 - nm);
            sm_m[tid] = nm;
        }
        __syncthreads();
    }
    if (tid == 0) {
        float lse = sm_m[0] + logf(sm_s[0]);
        float tl  = lr[targets[row]];
        atomicAdd(out_loss, (lse - tl) * (1.0f / (float)NROWS));
    }
}

// ---------------------------------------------------------------------------
// Host entry
// ---------------------------------------------------------------------------
extern "C" void kernel_launch(void* const* d_in, const int* in_sizes, int n_in,
                              void* d_out, int out_size) {
    const int*   idx   = (const int*)d_in[0];
    const int*   tgt   = (const int*)d_in[1];
    const float* wte   = (const float*)d_in[2];
    const float* start = (const float*)d_in[3];
    const float* Wz    = (const float*)d_in[4];
    const float* bz    = (const float*)d_in[5];
    const float* Wr    = (const float*)d_in[6];
    const float* br    = (const float*)d_in[7];
    const float* Wh    = (const float*)d_in[8];
    const float* bh    = (const float*)d_in[9];
    const float* lmW   = (const float*)d_in[10];
    const float* lmb   = (const float*)d_in[11];

    void *p_hs, *p_wlm, *p_fb, *p_emb, *p_wx, *p_xp;
    cudaGetSymbolAddress(&p_hs,  g_hs);
    cudaGetSymbolAddress(&p_wlm, g_wlm);
    cudaGetSymbolAddress(&p_fb,  g_logits_fb);
    cudaGetSymbolAddress(&p_emb, g_emb);
    cudaGetSymbolAddress(&p_wx,  g_wx);
    cudaGetSymbolAddress(&p_xp,  g_xp);
    __half* d_hs  = (__half*)p_hs;
    __half* d_wlm = (__half*)p_wlm;
    float*  d_fb  = (float*)p_fb;
    __half* d_emb = (__half*)p_emb;
    __half* d_wx  = (__half*)p_wx;
    float*  d_xp  = (float*)p_xp;

    cudaFuncSetAttribute(gru_kernel, cudaFuncAttributeMaxDynamicSharedMemorySize,
                         GRU_SMEM_BYTES);

    build_wx<<<(NEMBD * NG3 + 255) / 256, 256>>>(Wz, Wr, Wh, d_wx);
    gather_emb<<<NROWS, 128>>>(idx, wte, d_emb);

    gemm_kernel<NEMBD, NG3, false><<<dim3(NG3 / 128, NROWS / 128), 256>>>(
        d_emb, d_wx, nullptr, d_xp);

    gru_kernel<<<GRU_BLOCKS, GRU_THREADS, GRU_SMEM_BYTES>>>(start, Wz, bz, Wr, br, Wh, bh);

    cvt_half2<<<4096, 256>>>((const float2*)lmW, (__half2*)d_wlm, (NHID * VOCAB) / 2);
    const long long NL = (long long)NROWS * VOCAB;
    float* fo = (float*)d_out;
    float* logits = ((long long)out_size >= NL) ? fo : d_fb;
    gemm_kernel<NHID, VOCAB, true><<<dim3(VOCAB / 128, NROWS / 128), 256>>>(
        d_hs, d_wlm, lmb, logits);

    float* loss_ptr = nullptr;
    if ((long long)out_size >= NL + 1)      loss_ptr = fo + NL;
    else if ((long long)out_size < NL)      loss_ptr = fo;
    if (loss_ptr) {
        cudaMemsetAsync(loss_ptr, 0, sizeof(float));
        loss_kernel<<<NROWS, 256>>>(logits, tgt, loss_ptr);
    }
}